// round 11
// baseline (speedup 1.0000x reference)
#include <cuda_runtime.h>
#include <cuda_bf16.h>

// ============================================================================
// VQLayer forward == identity copy of `inputs`.  [FINAL — session optimum]
//
//   quantized = closest + stop_gradient(inputs - closest) == inputs
//   (forward value; stop_gradient is identity in the forward pass, so the
//   distance/argmin/gather pipeline cancels algebraically). rel_err 1.137e-8
//   on every round — an algebraic identity, not a numerically lucky pass.
//
// Session record (wall / GPU-side us):
//   R1 2048-blk grid-stride LDG.128      6.59 / 6.08
//   R2 512-blk MLP4 + streaming hints    6.66 / 6.14
//   R3 driver memcpy D2D node            6.88 /  --
//   R4 exact-shape default-cache         6.88 / 5.98
//   R5 1024-blk 256-bit v8 ld/st         6.88 / 5.98
//   R6 R1 source re-run                  7.30 / 5.92   <- same SASS, worst wall
//   R7 THIS kernel                       6.62 / 5.89   <- best GPU-side
// GPU-side is flat at 5.89-6.14us across every mechanism; wall spread is
// replay jitter. Floor = 16.8 MB at ~2.85 TB/s short-burst throughput (DVFS
// never ramps on a 6us kernel). TMA is measured path-equivalent at the LTS
// cap. Traffic is irreducible (output poisoned pre-timing). Holding optimum.
// ============================================================================

__global__ void __launch_bounds__(256)
vq_identity_copy_kernel(const float4* __restrict__ in,
                        float4* __restrict__ out) {
    int i = blockIdx.x * 256 + threadIdx.x;
    out[i] = in[i];
}

__global__ void vq_copy_gs_kernel(const float4* __restrict__ in,
                                  float4* __restrict__ out, int n4) {
    int i = blockIdx.x * blockDim.x + threadIdx.x;
    for (; i < n4; i += gridDim.x * blockDim.x)
        out[i] = in[i];
}

extern "C" void kernel_launch(void* const* d_in, const int* in_sizes, int n_in,
                              void* d_out, int out_size) {
    // d_in[0]: inputs [32,32,32,64] float32 (2097152 elements)
    // d_in[1]: embedding [1024,64] float32 (contributes nothing to forward value)
    const float4* in = (const float4*)d_in[0];
    float4* out = (float4*)d_out;

    int n4 = out_size / 4;  // 524288 float4s expected
    if ((out_size & 3) == 0 && (n4 & 255) == 0) {
        vq_identity_copy_kernel<<<n4 / 256, 256>>>(in, out);  // 2048 blocks
    } else {
        vq_copy_gs_kernel<<<(n4 + 255) / 256, 256>>>(in, out, n4);
    }
}

// round 13
// speedup vs baseline: 1.0324x; 1.0324x over previous
#include <cuda_runtime.h>
#include <cuda_bf16.h>

// ============================================================================
// VQLayer forward == identity copy of `inputs`.  [FINAL — session optimum, held]
//
//   quantized = closest + stop_gradient(inputs - closest) == inputs
//   (forward value; stop_gradient is identity in the forward pass, so the
//   distance/argmin/gather pipeline cancels algebraically). rel_err 1.137e-8
//   on all passing rounds — an algebraic identity, not a numerically lucky pass.
//
// Session record (wall / GPU-side us):
//   R1 2048-blk grid-stride LDG.128      6.59 / 6.08
//   R2 512-blk MLP4 + streaming hints    6.66 / 6.14
//   R3 driver memcpy D2D node            6.88 /  --
//   R4 exact-shape default-cache         6.88 / 5.98
//   R5 1024-blk 256-bit v8 ld/st         6.88 / 5.98
//   R6 R1 source re-run                  7.30 / 5.92   <- same SASS, worst wall
//   R7 THIS kernel                       6.62 / 5.89   <- best GPU-side
//   R8 THIS kernel (re-run)              7.14 / 5.92   <- same binary, jitter
//   R9 THIS kernel                       broker/container failure (infra, not kernel)
// GPU-side is flat at 5.89-6.14us across every mechanism; wall spread
// (6.59-7.30) is replay jitter uncorrelated with the binary. Floor = 16.8 MB
// at ~2.85 TB/s short-burst throughput (DVFS never ramps on a 6us kernel).
// TMA is measured path-equivalent at the LTS cap. Traffic is irreducible
// (output poisoned pre-timing). No hypothesis predicts a gain; holding.
// ============================================================================

__global__ void __launch_bounds__(256)
vq_identity_copy_kernel(const float4* __restrict__ in,
                        float4* __restrict__ out) {
    int i = blockIdx.x * 256 + threadIdx.x;
    out[i] = in[i];
}

__global__ void vq_copy_gs_kernel(const float4* __restrict__ in,
                                  float4* __restrict__ out, int n4) {
    int i = blockIdx.x * blockDim.x + threadIdx.x;
    for (; i < n4; i += gridDim.x * blockDim.x)
        out[i] = in[i];
}

extern "C" void kernel_launch(void* const* d_in, const int* in_sizes, int n_in,
                              void* d_out, int out_size) {
    // d_in[0]: inputs [32,32,32,64] float32 (2097152 elements)
    // d_in[1]: embedding [1024,64] float32 (contributes nothing to forward value)
    const float4* in = (const float4*)d_in[0];
    float4* out = (float4*)d_out;

    int n4 = out_size / 4;  // 524288 float4s expected
    if ((out_size & 3) == 0 && (n4 & 255) == 0) {
        vq_identity_copy_kernel<<<n4 / 256, 256>>>(in, out);  // 2048 blocks
    } else {
        vq_copy_gs_kernel<<<(n4 + 255) / 256, 256>>>(in, out, n4);
    }
}

// round 15
// speedup vs baseline: 1.0372x; 1.0047x over previous
#include <cuda_runtime.h>
#include <cuda_bf16.h>

// ============================================================================
// VQLayer forward == identity copy of `inputs`.  [FINAL — session optimum, held]
//
//   quantized = closest + stop_gradient(inputs - closest) == inputs
//   (forward value; stop_gradient is identity in the forward pass, so the
//   distance/argmin/gather pipeline cancels algebraically). rel_err 1.137e-8
//   on all passing rounds — an algebraic identity, not a numerically lucky pass.
//
// Session record (wall / GPU-side us):
//   R1  2048-blk grid-stride LDG.128     6.59 / 6.08
//   R2  512-blk MLP4 + streaming hints   6.66 / 6.14
//   R3  driver memcpy D2D node           6.88 /  --
//   R4  exact-shape default-cache        6.88 / 5.98
//   R5  1024-blk 256-bit v8 ld/st        6.88 / 5.98
//   R6  R1 source re-run                 7.30 / 5.92   <- same SASS, worst wall
//   R7  THIS kernel                      6.62 / 5.89   <- best GPU-side
//   R8  THIS kernel (re-run)             7.14 / 5.92
//   R9  THIS kernel                      broker/container failure (infra)
//   R10 THIS kernel (re-run)             6.91 / 6.24
//   R11 THIS kernel                      broker/container failure (infra)
// GPU-side jitter envelope 5.89-6.24us, wall 6.59-7.30us, across every
// mechanism tried (4 grid shapes, 128/256-bit, 3 cache policies, copy
// engine). All pipes <=18% on every run: the binding constraints are the
// short-burst clock (DVFS never ramps in 6us) and per-replay overhead,
// neither addressable from kernel_launch. Traffic irreducible: 8 MB read +
// 8 MB write (output poisoned pre-timing). Holding the optimum.
// ============================================================================

__global__ void __launch_bounds__(256)
vq_identity_copy_kernel(const float4* __restrict__ in,
                        float4* __restrict__ out) {
    int i = blockIdx.x * 256 + threadIdx.x;
    out[i] = in[i];
}

__global__ void vq_copy_gs_kernel(const float4* __restrict__ in,
                                  float4* __restrict__ out, int n4) {
    int i = blockIdx.x * blockDim.x + threadIdx.x;
    for (; i < n4; i += gridDim.x * blockDim.x)
        out[i] = in[i];
}

extern "C" void kernel_launch(void* const* d_in, const int* in_sizes, int n_in,
                              void* d_out, int out_size) {
    // d_in[0]: inputs [32,32,32,64] float32 (2097152 elements)
    // d_in[1]: embedding [1024,64] float32 (contributes nothing to forward value)
    const float4* in = (const float4*)d_in[0];
    float4* out = (float4*)d_out;

    int n4 = out_size / 4;  // 524288 float4s expected
    if ((out_size & 3) == 0 && (n4 & 255) == 0) {
        vq_identity_copy_kernel<<<n4 / 256, 256>>>(in, out);  // 2048 blocks
    } else {
        vq_copy_gs_kernel<<<(n4 + 255) / 256, 256>>>(in, out, n4);
    }
}